// round 1
// baseline (speedup 1.0000x reference)
#include <cuda_runtime.h>
#include <math.h>

// Caps1D dynamic routing, fused single kernel.
// One CTA per (b,k) pair. u_ji[r,p] for the pair is held entirely in
// registers (5 rows/thread x 16 = 80 regs @ 512 threads). W[k] is streamed
// through shared memory in 512-row chunks with coalesced float4 loads and
// a 68-float padded row stride for conflict-free LDS.128 reads.
// All 3 routing iterations run register-resident with small shfl/smem
// block reductions; only classes[b,k] is written out.

namespace {
constexpr int T     = 512;   // threads per CTA
constexpr int Rdim  = 2336;  // routes
constexpr int Mdim  = 4;     // input capsule dim
constexpr int Pdim  = 16;    // output capsule dim
constexpr int Kdim  = 2;     // classes/capsule groups
constexpr int Bdim  = 1024;  // batch
constexpr int J     = 5;     // ceil(R/T) row slots per thread
constexpr int WROW  = 68;    // padded smem row stride (floats): 68 mod 32 = 4 -> conflict-free
constexpr int NW    = T / 32;
constexpr int SMEM_FLOATS = T * WROW + NW * Pdim + Pdim + 8;
}

__device__ __forceinline__ float blockReduceSumF(float v, float* red, int lane, int wid) {
    #pragma unroll
    for (int o = 16; o >= 1; o >>= 1) v += __shfl_xor_sync(0xffffffffu, v, o);
    __syncthreads();
    if (lane == 0) red[wid] = v;
    __syncthreads();
    float r = 0.f;
    #pragma unroll
    for (int w = 0; w < NW; ++w) r += red[w];  // broadcast LDS, conflict-free
    return r;
}

__device__ __forceinline__ float blockReduceMaxF(float v, float* red, int lane, int wid) {
    #pragma unroll
    for (int o = 16; o >= 1; o >>= 1) v = fmaxf(v, __shfl_xor_sync(0xffffffffu, v, o));
    __syncthreads();
    if (lane == 0) red[wid] = v;
    __syncthreads();
    float r = -3.0e38f;
    #pragma unroll
    for (int w = 0; w < NW; ++w) r = fmaxf(r, red[w]);
    return r;
}

// Block-reduce s[16], scale by `pre`, apply squash.
// Result: vbuf[p] = v[p] (post-squash vector), misc[0] = norm(pre*S)^2 sum.
__device__ __forceinline__ void blockSquash(float s[Pdim], float* red, float* vbuf,
                                            float* misc, float pre,
                                            int t, int lane, int wid) {
    #pragma unroll
    for (int o = 16; o >= 1; o >>= 1) {
        #pragma unroll
        for (int p = 0; p < Pdim; p++) s[p] += __shfl_xor_sync(0xffffffffu, s[p], o);
    }
    __syncthreads();
    if (lane == 0) {
        #pragma unroll
        for (int p = 0; p < Pdim; p++) red[wid * Pdim + p] = s[p];
    }
    __syncthreads();
    if (t < Pdim) {  // warp 0, lanes 0..15
        float acc = 0.f;
        #pragma unroll
        for (int w = 0; w < NW; ++w) acc += red[w * Pdim + t];
        acc *= pre;
        float nrm = acc * acc;
        #pragma unroll
        for (int o = 8; o >= 1; o >>= 1) nrm += __shfl_xor_sync(0x0000ffffu, nrm, o);
        // squash: v = t_vec * sqrt(norm) / (1 + norm)
        float vf = sqrtf(nrm) / (1.f + nrm);
        vbuf[t] = acc * vf;
        if (t == 0) misc[0] = nrm;
    }
    __syncthreads();
}

__global__ __launch_bounds__(T, 1)
void caps_routing_kernel(const float* __restrict__ u,
                         const float* __restrict__ W,
                         float* __restrict__ out) {
    extern __shared__ float sm[];
    float* Wbuf = sm;                       // [T][WROW]
    float* red  = sm + T * WROW;            // [NW*Pdim] (also reused for scalar reduces)
    float* vbuf = red + NW * Pdim;          // [Pdim]
    float* misc = vbuf + Pdim;              // norm slot

    const int t    = threadIdx.x;
    const int lane = t & 31;
    const int wid  = t >> 5;
    const int bid  = blockIdx.x;
    const int b    = bid >> 1;   // consecutive CTAs share b -> u[b] L2 reuse
    const int k    = bid & 1;

    // ------- Phase 1: compute u_ji into registers -------
    float uji[J][Pdim];
    #pragma unroll
    for (int j = 0; j < J; j++)
        #pragma unroll
        for (int p = 0; p < Pdim; p++) uji[j][p] = 0.f;

    const float4* Wg_base = reinterpret_cast<const float4*>(W) + (size_t)k * Rdim * (Mdim * Pdim / 4);
    const float4* ug      = reinterpret_cast<const float4*>(u) + (size_t)b * Rdim;  // one float4 per row (M=4)

    #pragma unroll
    for (int j = 0; j < J; j++) {
        const int base = j * T;
        const int rows = (base + T <= Rdim) ? T : (Rdim - base);   // 512,512,512,512,288
        const int n4   = rows * (Mdim * Pdim / 4);                 // rows*16 float4s
        const float4* Wg = Wg_base + (size_t)base * (Mdim * Pdim / 4);

        // coalesced stage: global row-major -> smem padded rows
        for (int idx = t; idx < n4; idx += T) {
            int rl = idx >> 4;
            int q  = idx & 15;
            float4 w = Wg[idx];
            *reinterpret_cast<float4*>(&Wbuf[rl * WROW + q * 4]) = w;
        }
        __syncthreads();

        if (t < rows) {
            float4 uv = ug[base + t];
            float um[4] = {uv.x, uv.y, uv.z, uv.w};
            const float4* wr4 = reinterpret_cast<const float4*>(&Wbuf[t * WROW]);
            #pragma unroll
            for (int m = 0; m < Mdim; m++) {
                #pragma unroll
                for (int q = 0; q < Pdim / 4; q++) {
                    float4 wv = wr4[m * (Pdim / 4) + q];   // conflict-free LDS.128
                    uji[j][q * 4 + 0] = fmaf(um[m], wv.x, uji[j][q * 4 + 0]);
                    uji[j][q * 4 + 1] = fmaf(um[m], wv.y, uji[j][q * 4 + 1]);
                    uji[j][q * 4 + 2] = fmaf(um[m], wv.z, uji[j][q * 4 + 2]);
                    uji[j][q * 4 + 3] = fmaf(um[m], wv.w, uji[j][q * 4 + 3]);
                }
            }
        }
        __syncthreads();
    }

    const bool valid4 = (t < Rdim - 4 * T);  // t < 288; slots j=0..3 always valid

    // ------- Phase 2: routing iterations (register resident) -------
    float d[J];  // routing logits b[r] (scalar per route)
    #pragma unroll
    for (int j = 0; j < J; j++) d[j] = 0.f;

    float vv[Pdim];

    // ---- iteration 0: c = 1/R uniform ----
    {
        float s[Pdim];
        #pragma unroll
        for (int p = 0; p < Pdim; p++) {
            float acc = 0.f;
            #pragma unroll
            for (int j = 0; j < J; j++) acc += uji[j][p];
            s[p] = acc;
        }
        blockSquash(s, red, vbuf, misc, 1.0f / (float)Rdim, t, lane, wid);
        #pragma unroll
        for (int p = 0; p < Pdim; p++) vv[p] = vbuf[p];
        #pragma unroll
        for (int j = 0; j < J; j++) {
            float dd = 0.f;
            #pragma unroll
            for (int p = 0; p < Pdim; p++) dd = fmaf(uji[j][p], vv[p], dd);
            d[j] += dd;
        }
    }

    // ---- iterations 1 and 2 ----
    #pragma unroll
    for (int it = 1; it < 3; ++it) {
        // softmax over routes of d
        float lmax = -3.0e38f;
        #pragma unroll
        for (int j = 0; j < J - 1; j++) lmax = fmaxf(lmax, d[j]);
        if (valid4) lmax = fmaxf(lmax, d[J - 1]);
        float gmax = blockReduceMaxF(lmax, red, lane, wid);

        float e[J];
        float lsum = 0.f;
        #pragma unroll
        for (int j = 0; j < J - 1; j++) { e[j] = __expf(d[j] - gmax); lsum += e[j]; }
        e[J - 1] = valid4 ? __expf(d[J - 1] - gmax) : 0.f;
        lsum += e[J - 1];
        float Z = blockReduceSumF(lsum, red, lane, wid);

        // S = sum_r exp_r * u_ji[r,:]  (1/Z folded into squash pre-scale)
        float s[Pdim];
        #pragma unroll
        for (int p = 0; p < Pdim; p++) {
            float acc = 0.f;
            #pragma unroll
            for (int j = 0; j < J; j++) acc = fmaf(e[j], uji[j][p], acc);
            s[p] = acc;
        }
        blockSquash(s, red, vbuf, misc, 1.0f / Z, t, lane, wid);

        if (it == 2) break;  // final v: only its norm matters

        #pragma unroll
        for (int p = 0; p < Pdim; p++) vv[p] = vbuf[p];
        #pragma unroll
        for (int j = 0; j < J; j++) {
            float dd = 0.f;
            #pragma unroll
            for (int p = 0; p < Pdim; p++) dd = fmaf(uji[j][p], vv[p], dd);
            d[j] += dd;
        }
    }

    // classes = ||squash(S2)|| = norm / (1 + norm)
    if (t == 0) {
        float nrm = misc[0];
        out[bid] = nrm / (1.f + nrm);
    }
}

extern "C" void kernel_launch(void* const* d_in, const int* in_sizes, int n_in,
                              void* d_out, int out_size) {
    const float* u = (const float*)d_in[0];   // [B, R, M] fp32
    const float* W = (const float*)d_in[1];   // [K, R, M, P] fp32
    float* out = (float*)d_out;               // [B, K] fp32

    cudaFuncSetAttribute(caps_routing_kernel,
                         cudaFuncAttributeMaxDynamicSharedMemorySize,
                         SMEM_FLOATS * (int)sizeof(float));

    caps_routing_kernel<<<Bdim * Kdim, T, SMEM_FLOATS * (int)sizeof(float)>>>(u, W, out);
}

// round 4
// speedup vs baseline: 1.3611x; 1.3611x over previous
#include <cuda_runtime.h>
#include <cuda_fp16.h>
#include <math.h>

// Caps1D dynamic routing — round 2.
// One CTA per (b,k). Phase 1: direct, fully-coalesced LDG of W/u from L2
// (no smem staging, no barriers), lane l owns (row-subgroup l>>2, P-quad l&3).
// u_ji stored register-resident as packed fp16 (half2 x2 per round) so that
// 2 CTAs fit per SM (__launch_bounds__(512,2), 64 regs). All accumulation fp32.
// Routing logits distributed across quad lanes (width-4 shfl broadcast).

namespace {
constexpr int T    = 512;
constexpr int Rdim = 2336;
constexpr int Pdim = 16;
constexpr int Kdim = 2;
constexpr int Bdim = 1024;
constexpr int NW   = T / 32;           // 16 warps
constexpr int NG   = Rdim / 8;         // 292 groups of 8 rows
constexpr int NR   = (NG + NW - 1)/NW; // 19 rounds max per warp
constexpr int ND   = (NR + 3) / 4;     // 5 distributed logit slots per lane
}

__device__ __forceinline__ float blockMaxF(float v, volatile float* red, int lane, int wid) {
    #pragma unroll
    for (int o = 16; o >= 1; o >>= 1) v = fmaxf(v, __shfl_xor_sync(0xffffffffu, v, o));
    __syncthreads();
    if (lane == 0) red[wid] = v;
    __syncthreads();
    float r = -3.0e38f;
    #pragma unroll
    for (int w = 0; w < NW; ++w) r = fmaxf(r, red[w]);
    return r;
}

__device__ __forceinline__ float blockSumF(float v, volatile float* red, int lane, int wid) {
    #pragma unroll
    for (int o = 16; o >= 1; o >>= 1) v += __shfl_xor_sync(0xffffffffu, v, o);
    __syncthreads();
    if (lane == 0) red[wid] = v;
    __syncthreads();
    float r = 0.f;
    #pragma unroll
    for (int w = 0; w < NW; ++w) r += red[w];
    return r;
}

__global__ __launch_bounds__(T, 2)
void caps_routing_kernel(const float* __restrict__ u,
                         const float* __restrict__ W,
                         float* __restrict__ out) {
    __shared__ float redS[NW * Pdim];   // per-warp S partials
    __shared__ float redW[NW];          // scalar reductions
    __shared__ float vbuf[Pdim];        // broadcast v
    __shared__ float misc;              // final norm

    const int t    = threadIdx.x;
    const int lane = t & 31;
    const int wid  = t >> 5;
    const int q    = lane & 3;          // P-quad: p = 4*q + c
    const int sub  = lane >> 2;         // row subgroup 0..7
    const int bid  = blockIdx.x;
    const int b    = bid >> 1;
    const int k    = bid & 1;

    const float4* U4 = reinterpret_cast<const float4*>(u) + (size_t)b * Rdim;
    const float4* W4 = reinterpret_cast<const float4*>(W) + (size_t)k * Rdim * 16;

    // ---------------- Phase 1: u_ji -> fp16 registers ----------------
    __half2 ulo[NR], uhi[NR];

    #pragma unroll
    for (int i = 0; i < NR; i++) {
        const int g = i * NW + wid;              // row group (warp-uniform)
        float a0 = 0.f, a1 = 0.f, a2 = 0.f, a3 = 0.f;
        if (g < NG) {
            const int row = g * 8 + sub;
            float4 u4 = U4[row];                 // broadcast across quad lanes
            const float4* wr = W4 + (size_t)row * 16 + q;
            float4 w0 = wr[0];                   // m = 0..3, 64B/lane-group, coalesced
            float4 w1 = wr[4];
            float4 w2 = wr[8];
            float4 w3 = wr[12];
            a0 = fmaf(u4.x, w0.x, fmaf(u4.y, w1.x, fmaf(u4.z, w2.x, u4.w * w3.x)));
            a1 = fmaf(u4.x, w0.y, fmaf(u4.y, w1.y, fmaf(u4.z, w2.y, u4.w * w3.y)));
            a2 = fmaf(u4.x, w0.z, fmaf(u4.y, w1.z, fmaf(u4.z, w2.z, u4.w * w3.z)));
            a3 = fmaf(u4.x, w0.w, fmaf(u4.y, w1.w, fmaf(u4.z, w2.w, u4.w * w3.w)));
        }
        ulo[i] = __floats2half2_rn(a0, a1);
        uhi[i] = __floats2half2_rn(a2, a3);
    }

    // ---------------- Phase 2: routing, register resident ----------------
    // Distributed logits: lane owns rounds i with (i&3)==q, slot i>>2.
    float dloc[ND];
    #pragma unroll
    for (int s = 0; s < ND; s++) {
        const int i = 4 * s + q;
        const bool ok = (i < NR) && (i * NW + wid < NG);
        dloc[s] = ok ? 0.f : -1.0e30f;
    }

    float v0, v1, v2, v3;  // current v quad (p = 4q+c)

    // ---- helper lambdas (inlined) ----
    auto reduce_squash = [&](float s0, float s1, float s2, float s3,
                             float pre, bool need_v) {
        // sum over lanes with same quad (bits 2..4), then across warps
        #pragma unroll
        for (int o = 4; o <= 16; o <<= 1) {
            s0 += __shfl_xor_sync(0xffffffffu, s0, o);
            s1 += __shfl_xor_sync(0xffffffffu, s1, o);
            s2 += __shfl_xor_sync(0xffffffffu, s2, o);
            s3 += __shfl_xor_sync(0xffffffffu, s3, o);
        }
        __syncthreads();
        if (lane < 4) {
            float* dst = &redS[wid * Pdim + lane * 4];
            dst[0] = s0; dst[1] = s1; dst[2] = s2; dst[3] = s3;
        }
        __syncthreads();
        if (t < Pdim) {
            float acc = 0.f;
            #pragma unroll
            for (int w = 0; w < NW; ++w) acc += redS[w * Pdim + t];
            acc *= pre;
            float nrm = acc * acc;
            #pragma unroll
            for (int o = 8; o >= 1; o >>= 1) nrm += __shfl_xor_sync(0x0000ffffu, nrm, o);
            if (need_v) {
                float vf = sqrtf(nrm) / (1.f + nrm);
                vbuf[t] = acc * vf;
            }
            if (t == 0) misc = nrm;
        }
        __syncthreads();
    };

    // ---- iteration 0: c uniform = 1/R ----
    {
        float s0 = 0.f, s1 = 0.f, s2 = 0.f, s3 = 0.f;
        #pragma unroll
        for (int i = 0; i < NR; i++) {
            float2 lo = __half22float2(ulo[i]);
            float2 hi = __half22float2(uhi[i]);
            s0 += lo.x; s1 += lo.y; s2 += hi.x; s3 += hi.y;
        }
        reduce_squash(s0, s1, s2, s3, 1.0f / (float)Rdim, true);
        v0 = vbuf[4 * q + 0]; v1 = vbuf[4 * q + 1];
        v2 = vbuf[4 * q + 2]; v3 = vbuf[4 * q + 3];
        // logit update: d[r] += <u_ji[r,:], v>
        #pragma unroll
        for (int i = 0; i < NR; i++) {
            float2 lo = __half22float2(ulo[i]);
            float2 hi = __half22float2(uhi[i]);
            float dd = fmaf(lo.x, v0, fmaf(lo.y, v1, fmaf(hi.x, v2, hi.y * v3)));
            dd += __shfl_xor_sync(0xffffffffu, dd, 1);
            dd += __shfl_xor_sync(0xffffffffu, dd, 2);
            if (q == (i & 3)) dloc[i >> 2] += dd;
        }
    }

    // ---- iterations 1, 2 ----
    #pragma unroll
    for (int it = 1; it < 3; ++it) {
        float lmax = -3.0e38f;
        #pragma unroll
        for (int s = 0; s < ND; s++) lmax = fmaxf(lmax, dloc[s]);
        const float gmax = blockMaxF(lmax, redW, lane, wid);

        float lsum = 0.f;
        float s0 = 0.f, s1 = 0.f, s2 = 0.f, s3 = 0.f;
        #pragma unroll
        for (int i = 0; i < NR; i++) {
            float di = __shfl_sync(0xffffffffu, dloc[i >> 2], i & 3, 4);
            float e  = __expf(di - gmax);        // invalid rows: di=-1e30 -> e=0
            lsum += e;
            float2 lo = __half22float2(ulo[i]);
            float2 hi = __half22float2(uhi[i]);
            s0 = fmaf(e, lo.x, s0); s1 = fmaf(e, lo.y, s1);
            s2 = fmaf(e, hi.x, s2); s3 = fmaf(e, hi.y, s3);
        }
        // every row's e counted 4x (quad replication) in the block sum
        const float Zb = blockSumF(lsum, redW, lane, wid);
        reduce_squash(s0, s1, s2, s3, 4.0f / Zb, it != 2);

        if (it == 2) break;
        v0 = vbuf[4 * q + 0]; v1 = vbuf[4 * q + 1];
        v2 = vbuf[4 * q + 2]; v3 = vbuf[4 * q + 3];
        #pragma unroll
        for (int i = 0; i < NR; i++) {
            float2 lo = __half22float2(ulo[i]);
            float2 hi = __half22float2(uhi[i]);
            float dd = fmaf(lo.x, v0, fmaf(lo.y, v1, fmaf(hi.x, v2, hi.y * v3)));
            dd += __shfl_xor_sync(0xffffffffu, dd, 1);
            dd += __shfl_xor_sync(0xffffffffu, dd, 2);
            if (q == (i & 3)) dloc[i >> 2] += dd;
        }
    }

    if (t == 0) {
        const float nrm = misc;
        out[bid] = nrm / (1.f + nrm);
    }
}

extern "C" void kernel_launch(void* const* d_in, const int* in_sizes, int n_in,
                              void* d_out, int out_size) {
    const float* u = (const float*)d_in[0];   // [B, R, M] fp32
    const float* W = (const float*)d_in[1];   // [K, R, M, P] fp32
    float* out = (float*)d_out;               // [B, K] fp32

    caps_routing_kernel<<<Bdim * Kdim, T>>>(u, W, out);
}

// round 5
// speedup vs baseline: 1.6105x; 1.1832x over previous
#include <cuda_runtime.h>
#include <cuda_fp16.h>
#include <math.h>

// Caps1D dynamic routing — round 5.
// Prologue kernel converts W (fp32, 1.2 MB) into a lane-packed fp16 scratch
// ([k][group][chunk][lane] x int4) so the main kernel's phase 1 is two
// perfectly-coalesced LDG.128 per row-round, halving L2/L1 W traffic
// (1.22 GB -> 0.61 GB). One CTA per (b,k); u_ji register-resident fp16;
// all accumulation fp32; 2 CTAs/SM.

namespace {
constexpr int T    = 512;
constexpr int Rdim = 2336;
constexpr int Pdim = 16;
constexpr int Kdim = 2;
constexpr int Bdim = 1024;
constexpr int NW   = T / 32;            // 16 warps
constexpr int NG   = Rdim / 8;          // 292 groups of 8 rows
constexpr int NR   = (NG + NW - 1)/NW;  // 19 rounds per warp
constexpr int ND   = (NR + 3) / 4;      // 5 distributed logit slots per lane
constexpr int WCONV = Kdim * NG * 2 * 32;  // int4 elements in packed W
}

// Packed fp16 W scratch: [k][g][chunk][lane] -> int4 (8 halfs: 2 m-values x 4 p)
__device__ int4 W2dev[WCONV];

__global__ void convert_w_kernel(const float* __restrict__ W) {
    const int idx = blockIdx.x * blockDim.x + threadIdx.x;
    if (idx >= WCONV) return;
    const int lane = idx & 31;
    const int c    = (idx >> 5) & 1;       // m-chunk: m = {2c, 2c+1}
    const int g    = (idx >> 6) % NG;
    const int k    = idx / (NG * 64);
    const int sub  = lane >> 2;
    const int q    = lane & 3;
    const int row  = g * 8 + sub;

    const float4* src = reinterpret_cast<const float4*>(W)
                      + ((size_t)(k * Rdim + row)) * 16 + q;  // float4 index: m*4 + q
    float4 w0 = src[(2 * c + 0) * 4];
    float4 w1 = src[(2 * c + 1) * 4];

    __half2 h0 = __floats2half2_rn(w0.x, w0.y);
    __half2 h1 = __floats2half2_rn(w0.z, w0.w);
    __half2 h2 = __floats2half2_rn(w1.x, w1.y);
    __half2 h3 = __floats2half2_rn(w1.z, w1.w);
    int4 o;
    o.x = *reinterpret_cast<int*>(&h0);
    o.y = *reinterpret_cast<int*>(&h1);
    o.z = *reinterpret_cast<int*>(&h2);
    o.w = *reinterpret_cast<int*>(&h3);
    W2dev[idx] = o;
}

__device__ __forceinline__ float blockMaxF(float v, volatile float* red, int lane, int wid) {
    #pragma unroll
    for (int o = 16; o >= 1; o >>= 1) v = fmaxf(v, __shfl_xor_sync(0xffffffffu, v, o));
    __syncthreads();
    if (lane == 0) red[wid] = v;
    __syncthreads();
    float r = -3.0e38f;
    #pragma unroll
    for (int w = 0; w < NW; ++w) r = fmaxf(r, red[w]);
    return r;
}

__device__ __forceinline__ float blockSumF(float v, volatile float* red, int lane, int wid) {
    #pragma unroll
    for (int o = 16; o >= 1; o >>= 1) v += __shfl_xor_sync(0xffffffffu, v, o);
    __syncthreads();
    if (lane == 0) red[wid] = v;
    __syncthreads();
    float r = 0.f;
    #pragma unroll
    for (int w = 0; w < NW; ++w) r += red[w];
    return r;
}

__global__ __launch_bounds__(T, 2)
void caps_routing_kernel(const float* __restrict__ u,
                         float* __restrict__ out) {
    __shared__ float redS[NW * Pdim];
    __shared__ float redW[NW];
    __shared__ float vbuf[Pdim];
    __shared__ float misc;

    const int t    = threadIdx.x;
    const int lane = t & 31;
    const int wid  = t >> 5;
    const int q    = lane & 3;          // P-quad: p = 4*q + c
    const int sub  = lane >> 2;         // row subgroup 0..7
    const int bid  = blockIdx.x;
    const int b    = bid >> 1;
    const int k    = bid & 1;

    const float4* U4 = reinterpret_cast<const float4*>(u) + (size_t)b * Rdim;

    // ---------------- Phase 1: u_ji -> fp16 registers ----------------
    __half2 ulo[NR], uhi[NR];

    #pragma unroll
    for (int i = 0; i < NR; i++) {
        const int g = i * NW + wid;
        float a0 = 0.f, a1 = 0.f, a2 = 0.f, a3 = 0.f;
        if (g < NG) {
            const int row = g * 8 + sub;
            float4 u4 = U4[row];
            const int4* base = W2dev + ((size_t)(k * NG + g) * 2) * 32 + lane;
            int4 A = base[0];    // m0, m1
            int4 Bv = base[32];  // m2, m3
            float2 f0 = __half22float2(*reinterpret_cast<__half2*>(&A.x));  // m0 p0,p1
            float2 f1 = __half22float2(*reinterpret_cast<__half2*>(&A.y));  // m0 p2,p3
            float2 f2 = __half22float2(*reinterpret_cast<__half2*>(&A.z));  // m1 p0,p1
            float2 f3 = __half22float2(*reinterpret_cast<__half2*>(&A.w));  // m1 p2,p3
            float2 f4 = __half22float2(*reinterpret_cast<__half2*>(&Bv.x)); // m2 p0,p1
            float2 f5 = __half22float2(*reinterpret_cast<__half2*>(&Bv.y)); // m2 p2,p3
            float2 f6 = __half22float2(*reinterpret_cast<__half2*>(&Bv.z)); // m3 p0,p1
            float2 f7 = __half22float2(*reinterpret_cast<__half2*>(&Bv.w)); // m3 p2,p3
            a0 = fmaf(u4.x, f0.x, fmaf(u4.y, f2.x, fmaf(u4.z, f4.x, u4.w * f6.x)));
            a1 = fmaf(u4.x, f0.y, fmaf(u4.y, f2.y, fmaf(u4.z, f4.y, u4.w * f6.y)));
            a2 = fmaf(u4.x, f1.x, fmaf(u4.y, f3.x, fmaf(u4.z, f5.x, u4.w * f7.x)));
            a3 = fmaf(u4.x, f1.y, fmaf(u4.y, f3.y, fmaf(u4.z, f5.y, u4.w * f7.y)));
        }
        ulo[i] = __floats2half2_rn(a0, a1);
        uhi[i] = __floats2half2_rn(a2, a3);
    }

    // ---------------- Phase 2: routing, register resident ----------------
    float dloc[ND];
    #pragma unroll
    for (int s = 0; s < ND; s++) {
        const int i = 4 * s + q;
        const bool ok = (i < NR) && (i * NW + wid < NG);
        dloc[s] = ok ? 0.f : -1.0e30f;
    }

    float v0, v1, v2, v3;

    auto reduce_squash = [&](float s0, float s1, float s2, float s3,
                             float pre, bool need_v) {
        #pragma unroll
        for (int o = 4; o <= 16; o <<= 1) {
            s0 += __shfl_xor_sync(0xffffffffu, s0, o);
            s1 += __shfl_xor_sync(0xffffffffu, s1, o);
            s2 += __shfl_xor_sync(0xffffffffu, s2, o);
            s3 += __shfl_xor_sync(0xffffffffu, s3, o);
        }
        __syncthreads();
        if (lane < 4) {
            float* dst = &redS[wid * Pdim + lane * 4];
            dst[0] = s0; dst[1] = s1; dst[2] = s2; dst[3] = s3;
        }
        __syncthreads();
        if (t < Pdim) {
            float acc = 0.f;
            #pragma unroll
            for (int w = 0; w < NW; ++w) acc += redS[w * Pdim + t];
            acc *= pre;
            float nrm = acc * acc;
            #pragma unroll
            for (int o = 8; o >= 1; o >>= 1) nrm += __shfl_xor_sync(0x0000ffffu, nrm, o);
            if (need_v) {
                float vf = sqrtf(nrm) / (1.f + nrm);
                vbuf[t] = acc * vf;
            }
            if (t == 0) misc = nrm;
        }
        __syncthreads();
    };

    // ---- iteration 0: uniform c ----
    {
        float s0 = 0.f, s1 = 0.f, s2 = 0.f, s3 = 0.f;
        #pragma unroll
        for (int i = 0; i < NR; i++) {
            float2 lo = __half22float2(ulo[i]);
            float2 hi = __half22float2(uhi[i]);
            s0 += lo.x; s1 += lo.y; s2 += hi.x; s3 += hi.y;
        }
        reduce_squash(s0, s1, s2, s3, 1.0f / (float)Rdim, true);
        v0 = vbuf[4 * q + 0]; v1 = vbuf[4 * q + 1];
        v2 = vbuf[4 * q + 2]; v3 = vbuf[4 * q + 3];
        #pragma unroll
        for (int i = 0; i < NR; i++) {
            float2 lo = __half22float2(ulo[i]);
            float2 hi = __half22float2(uhi[i]);
            float dd = fmaf(lo.x, v0, fmaf(lo.y, v1, fmaf(hi.x, v2, hi.y * v3)));
            dd += __shfl_xor_sync(0xffffffffu, dd, 1);
            dd += __shfl_xor_sync(0xffffffffu, dd, 2);
            if (q == (i & 3)) dloc[i >> 2] += dd;
        }
    }

    // ---- iterations 1, 2 ----
    #pragma unroll
    for (int it = 1; it < 3; ++it) {
        float lmax = -3.0e38f;
        #pragma unroll
        for (int s = 0; s < ND; s++) lmax = fmaxf(lmax, dloc[s]);
        const float gmax = blockMaxF(lmax, redW, lane, wid);

        float lsum = 0.f;
        float s0 = 0.f, s1 = 0.f, s2 = 0.f, s3 = 0.f;
        #pragma unroll
        for (int i = 0; i < NR; i++) {
            float di = __shfl_sync(0xffffffffu, dloc[i >> 2], i & 3, 4);
            float e  = __expf(di - gmax);
            lsum += e;
            float2 lo = __half22float2(ulo[i]);
            float2 hi = __half22float2(uhi[i]);
            s0 = fmaf(e, lo.x, s0); s1 = fmaf(e, lo.y, s1);
            s2 = fmaf(e, hi.x, s2); s3 = fmaf(e, hi.y, s3);
        }
        const float Zb = blockSumF(lsum, redW, lane, wid);   // 4x replicated
        reduce_squash(s0, s1, s2, s3, 4.0f / Zb, it != 2);

        if (it == 2) break;
        v0 = vbuf[4 * q + 0]; v1 = vbuf[4 * q + 1];
        v2 = vbuf[4 * q + 2]; v3 = vbuf[4 * q + 3];
        #pragma unroll
        for (int i = 0; i < NR; i++) {
            float2 lo = __half22float2(ulo[i]);
            float2 hi = __half22float2(uhi[i]);
            float dd = fmaf(lo.x, v0, fmaf(lo.y, v1, fmaf(hi.x, v2, hi.y * v3)));
            dd += __shfl_xor_sync(0xffffffffu, dd, 1);
            dd += __shfl_xor_sync(0xffffffffu, dd, 2);
            if (q == (i & 3)) dloc[i >> 2] += dd;
        }
    }

    if (t == 0) {
        const float nrm = misc;
        out[bid] = nrm / (1.f + nrm);
    }
}

extern "C" void kernel_launch(void* const* d_in, const int* in_sizes, int n_in,
                              void* d_out, int out_size) {
    const float* u = (const float*)d_in[0];   // [B, R, M] fp32
    const float* W = (const float*)d_in[1];   // [K, R, M, P] fp32
    float* out = (float*)d_out;               // [B, K] fp32

    convert_w_kernel<<<(WCONV + 255) / 256, 256>>>(W);
    caps_routing_kernel<<<Bdim * Kdim, T>>>(u, out);
}

// round 7
// speedup vs baseline: 2.5291x; 1.5704x over previous
#include <cuda_runtime.h>
#include <cuda_fp16.h>
#include <math.h>

// Caps1D dynamic routing — round 6.
// Full-row ownership: thread t owns rows {t, t+512, ...} with all 16 P
// components (u_ji = 40 half2 regs). Softmax/logit work is lane-local (zero
// shuffles in sweeps, 10 exps total). Phase 1 is pure HFMA2 from a prologue-
// packed fp16 W ([k][j][c][512] int4, zero-filled tail) -> 8 coalesced
// LDG.128 per row, no conversions. S[16] block-reduced via value-splitting
// butterfly (24 shfl) + smem cross-warp stage. fp32 everywhere in phase 2.

namespace {
constexpr int T    = 512;
constexpr int Rdim = 2336;
constexpr int Pdim = 16;
constexpr int Kdim = 2;
constexpr int Bdim = 1024;
constexpr int NW   = T / 32;
constexpr int J    = 5;                    // rows per thread
constexpr int WCONV = Kdim * J * 8 * 512;  // int4 elements in packed W
}

// Packed fp16 W: [k][j][c][t] -> int4. c = 2*m + hc; int4 holds 4 half2
// covering p = hc*8 .. hc*8+7 for that m. Rows >= Rdim are zero.
__device__ int4 W2dev[WCONV];

__global__ void convert_w_kernel(const float* __restrict__ W) {
    const int idx = blockIdx.x * blockDim.x + threadIdx.x;
    if (idx >= WCONV) return;
    const int t  = idx & 511;
    const int c  = (idx >> 9) & 7;
    const int kj = idx >> 12;
    const int j  = kj % J;
    const int k  = kj / J;
    const int row = j * 512 + t;
    const int m   = c >> 1;
    const int hc  = c & 1;
    int4 o = make_int4(0, 0, 0, 0);
    if (row < Rdim) {
        const float4* src = reinterpret_cast<const float4*>(W)
                          + ((size_t)(k * Rdim + row) * 4 + m) * 4 + hc * 2;
        float4 a = src[0];
        float4 b = src[1];
        __half2 h0 = __floats2half2_rn(a.x, a.y);
        __half2 h1 = __floats2half2_rn(a.z, a.w);
        __half2 h2 = __floats2half2_rn(b.x, b.y);
        __half2 h3 = __floats2half2_rn(b.z, b.w);
        o.x = *reinterpret_cast<int*>(&h0);
        o.y = *reinterpret_cast<int*>(&h1);
        o.z = *reinterpret_cast<int*>(&h2);
        o.w = *reinterpret_cast<int*>(&h3);
    }
    W2dev[idx] = o;
}

__device__ __forceinline__ float blockMaxF(float v, volatile float* red, int lane, int wid) {
    #pragma unroll
    for (int o = 16; o >= 1; o >>= 1) v = fmaxf(v, __shfl_xor_sync(0xffffffffu, v, o));
    __syncthreads();
    if (lane == 0) red[wid] = v;
    __syncthreads();
    float r = -3.0e38f;
    #pragma unroll
    for (int w = 0; w < NW; ++w) r = fmaxf(r, red[w]);
    return r;
}

__device__ __forceinline__ float blockSumF(float v, volatile float* red, int lane, int wid) {
    #pragma unroll
    for (int o = 16; o >= 1; o >>= 1) v += __shfl_xor_sync(0xffffffffu, v, o);
    __syncthreads();
    if (lane == 0) red[wid] = v;
    __syncthreads();
    float r = 0.f;
    #pragma unroll
    for (int w = 0; w < NW; ++w) r += red[w];
    return r;
}

// Block-reduce s[16] across all 512 threads; scale by pre; squash.
// Value-splitting butterfly: xor16 and xor8 halve the component set per lane,
// xor4/2/1 reduce the remaining 4 components. Then smem cross-warp stage.
__device__ __forceinline__ void blockReduceS(const float* s, float* redS,
                                             float* vbuf, float* misc,
                                             float pre, bool need_v,
                                             int t, int lane, int wid) {
    const unsigned F = 0xffffffffu;
    float r8[8];
    {
        const bool hi = (lane & 16) != 0;
        #pragma unroll
        for (int i = 0; i < 8; i++) {
            float send = hi ? s[i] : s[8 + i];
            float recv = __shfl_xor_sync(F, send, 16);
            r8[i] = (hi ? s[8 + i] : s[i]) + recv;   // comps (hi*8 + i)
        }
    }
    float r4[4];
    {
        const bool hi = (lane & 8) != 0;
        #pragma unroll
        for (int i = 0; i < 4; i++) {
            float send = hi ? r8[i] : r8[4 + i];
            float recv = __shfl_xor_sync(F, send, 8);
            r4[i] = (hi ? r8[4 + i] : r8[i]) + recv; // comps (bit4*8 + bit3*4 + i)
        }
    }
    #pragma unroll
    for (int o = 4; o >= 1; o >>= 1) {
        #pragma unroll
        for (int i = 0; i < 4; i++) r4[i] += __shfl_xor_sync(F, r4[i], o);
    }
    __syncthreads();   // previous sweep's redS readers are done
    if ((lane & 7) == 0) {
        const int quad = ((lane >> 4) & 1) * 2 + ((lane >> 3) & 1);
        float4 v4 = make_float4(r4[0], r4[1], r4[2], r4[3]);
        *reinterpret_cast<float4*>(&redS[wid * Pdim + quad * 4]) = v4;
    }
    __syncthreads();
    if (t < Pdim) {
        float acc = 0.f;
        #pragma unroll
        for (int w = 0; w < NW; ++w) acc += redS[w * Pdim + t];
        acc *= pre;
        float nrm = acc * acc;
        #pragma unroll
        for (int o = 8; o >= 1; o >>= 1) nrm += __shfl_xor_sync(0x0000ffffu, nrm, o);
        if (need_v) {
            float vf = sqrtf(nrm) / (1.f + nrm);
            vbuf[t] = acc * vf;
        }
        if (t == 0) *misc = nrm;
    }
    __syncthreads();
}

__global__ __launch_bounds__(T, 2)
void caps_routing_kernel(const float* __restrict__ u,
                         float* __restrict__ out) {
    __shared__ float redS[NW * Pdim];
    __shared__ float redW[NW];
    __shared__ float vbuf[Pdim];
    __shared__ float miscS;

    const int t    = threadIdx.x;
    const int lane = t & 31;
    const int wid  = t >> 5;
    const int bid  = blockIdx.x;
    const int b    = bid >> 1;
    const int k    = bid & 1;

    const float4* U4 = reinterpret_cast<const float4*>(u) + (size_t)b * Rdim;

    // ---------------- Phase 1: u_ji -> fp16 registers (HFMA2) ----------------
    __half2 h[J][8];   // h[j][pp] = (p=2pp, p=2pp+1)

    #pragma unroll
    for (int j = 0; j < J; j++) {
        const int row  = j * 512 + t;
        const int rowc = row < Rdim ? row : Rdim - 1;   // clamp; W=0 masks result
        float4 u4 = U4[rowc];
        __half2 u0 = __float2half2_rn(u4.x);
        __half2 u1 = __float2half2_rn(u4.y);
        __half2 u2 = __float2half2_rn(u4.z);
        __half2 u3 = __float2half2_rn(u4.w);

        const int4* Wp = W2dev + (size_t)(k * J + j) * 8 * 512 + t;
        int4 wa[8];
        #pragma unroll
        for (int c = 0; c < 8; c++) wa[c] = Wp[c * 512];   // 8 coalesced LDG.128
        const __half2* wh = reinterpret_cast<const __half2*>(wa);

        #pragma unroll
        for (int hc = 0; hc < 2; hc++) {
            #pragma unroll
            for (int i = 0; i < 4; i++) {
                __half2 acc = __hmul2(u3, wh[(6 + hc) * 4 + i]);
                acc = __hfma2(u2, wh[(4 + hc) * 4 + i], acc);
                acc = __hfma2(u1, wh[(2 + hc) * 4 + i], acc);
                acc = __hfma2(u0, wh[(0 + hc) * 4 + i], acc);
                h[j][hc * 4 + i] = acc;
            }
        }
    }

    // ---------------- Phase 2: routing (lane-local rows) ----------------
    float d[J];
    #pragma unroll
    for (int j = 0; j < J; j++) d[j] = (j * 512 + t < Rdim) ? 0.f : -1.0e30f;

    // ---- iteration 0: uniform c ----
    {
        float s[Pdim];
        #pragma unroll
        for (int pp = 0; pp < 8; pp++) {
            __half2 acc = h[0][pp];
            #pragma unroll
            for (int j = 1; j < J; j++) acc = __hadd2(acc, h[j][pp]);  // tail rows are 0
            float2 f = __half22float2(acc);
            s[2 * pp]     = f.x;
            s[2 * pp + 1] = f.y;
        }
        blockReduceS(s, redS, vbuf, &miscS, 1.0f / (float)Rdim, true, t, lane, wid);

        float v[Pdim];
        #pragma unroll
        for (int p = 0; p < Pdim; p++) v[p] = vbuf[p];
        #pragma unroll
        for (int j = 0; j < J; j++) {
            float dd = 0.f;
            #pragma unroll
            for (int pp = 0; pp < 8; pp++) {
                float2 f = __half22float2(h[j][pp]);
                dd = fmaf(f.x, v[2 * pp], fmaf(f.y, v[2 * pp + 1], dd));
            }
            d[j] += dd;   // invalid rows: u_ji == 0 -> dd == 0
        }
    }

    // ---- iterations 1, 2 ----
    #pragma unroll
    for (int it = 1; it < 3; ++it) {
        float lmax = d[0];
        #pragma unroll
        for (int j = 1; j < J; j++) lmax = fmaxf(lmax, d[j]);
        const float gmax = blockMaxF(lmax, redW, lane, wid);

        float s[Pdim];
        #pragma unroll
        for (int p = 0; p < Pdim; p++) s[p] = 0.f;
        float lsum = 0.f;
        #pragma unroll
        for (int j = 0; j < J; j++) {
            float e = __expf(d[j] - gmax);   // invalid rows -> e = 0
            lsum += e;
            #pragma unroll
            for (int pp = 0; pp < 8; pp++) {
                float2 f = __half22float2(h[j][pp]);
                s[2 * pp]     = fmaf(e, f.x, s[2 * pp]);
                s[2 * pp + 1] = fmaf(e, f.y, s[2 * pp + 1]);
            }
        }
        const float Z = blockSumF(lsum, redW, lane, wid);
        blockReduceS(s, redS, vbuf, &miscS, 1.0f / Z, it != 2, t, lane, wid);

        if (it == 2) break;

        float v[Pdim];
        #pragma unroll
        for (int p = 0; p < Pdim; p++) v[p] = vbuf[p];
        #pragma unroll
        for (int j = 0; j < J; j++) {
            float dd = 0.f;
            #pragma unroll
            for (int pp = 0; pp < 8; pp++) {
                float2 f = __half22float2(h[j][pp]);
                dd = fmaf(f.x, v[2 * pp], fmaf(f.y, v[2 * pp + 1], dd));
            }
            d[j] += dd;
        }
    }

    if (t == 0) {
        const float nrm = miscS;
        out[bid] = nrm / (1.f + nrm);
    }
}

extern "C" void kernel_launch(void* const* d_in, const int* in_sizes, int n_in,
                              void* d_out, int out_size) {
    const float* u = (const float*)d_in[0];   // [B, R, M] fp32
    const float* W = (const float*)d_in[1];   // [K, R, M, P] fp32
    float* out = (float*)d_out;               // [B, K] fp32

    convert_w_kernel<<<(WCONV + 255) / 256, 256>>>(W);
    caps_routing_kernel<<<Bdim * Kdim, T>>>(u, out);
}